// round 12
// baseline (speedup 1.0000x reference)
#include <cuda_runtime.h>
#include <cstdint>

// ---------------------------------------------------------------------------
// Exact per-row top-k (k=2048), 128 rows x 262144 fp32 logits.
// OUTPUT: indices written as FLOAT32 values.
//   Round-10 crash proved d_out is 4-byte elements; round-9 diag proved our
//   int32 index bytes are correct yet scored rel_err == exactly 1.0 -- the
//   unique consistent explanation: the validator reads d_out as float32, so
//   integer index bits look like denormals (~0) and ||0-ref||/||ref|| == 1.0
//   exactly. Emitting (float)index makes the float-space comparison exact
//   (all indices < 2^24).
//
// (Round 11: GB300 container failed twice -- infra, not kernel. Resubmitting
//  unchanged to keep the experiment controlled.)
//
// Algorithm (verified byte-exact against host truth in round 9):
//   P1: 2048-bin histogram of top-11 bits of order-preserving uint key.
//   P2: warp suffix-scan -> threshold bin T containing the k-th largest.
//   P3: second pass: bins>T -> smem keys (hi < 2048); bin==T -> global side
//       buffer + refined histogram of key bits [10,21).
//   P4: warp suffix-scan -> refined threshold R within bin T.
//   P5: merge bin-T survivors (refined bits >= R): m in [2048, ~2100].
//   P6: bitonic sort of 4096 unique 64-bit keys (key32<<32 | ~idx):
//       value descending, index ascending on ties == stable jax.lax.top_k.
//   Emit top-2048 indices as float32.
// ---------------------------------------------------------------------------

#define ROWS    128
#define ROW_N   262144
#define K_OUT   2048
#define BINS    2048
#define CAPN    4096
#define TCAP    8192
#define NT      512

__device__ unsigned long long g_tmp[ROWS * TCAP];   // 8 MB side buffer

static __device__ __forceinline__ unsigned int ord32(unsigned int w) {
    return (w & 0x80000000u) ? ~w : (w | 0x80000000u);
}

// warp-0 suffix-scan over hist[BINS]: find bin B with
// count(bins > B) < need <= count(bins >= B)
static __device__ __forceinline__ void find_bin(const unsigned int* hist,
                                                unsigned int need, int* outB,
                                                int tid) {
    if (tid < 32) {
        const int BPL = BINS / 32;                    // 64 bins per lane
        unsigned int s = 0;
        for (int j = 0; j < BPL; j++) s += hist[tid * BPL + j];
        unsigned int v = s;
        #pragma unroll
        for (int d = 1; d < 32; d <<= 1) {
            unsigned int t = __shfl_down_sync(0xFFFFFFFFu, v, d);
            if (tid + d < 32) v += t;
        }
        unsigned int running = v - s;                 // totals of lanes above
        for (int j = BPL - 1; j >= 0; j--) {
            int b = tid * BPL + j;
            unsigned int n = hist[b];
            if (running < need && running + n >= need) *outB = b;
            running += n;
        }
    }
}

__global__ __launch_bounds__(NT, 1)
void topk_kernel(const float* __restrict__ logits, float* __restrict__ out) {
    __shared__ unsigned int       hist[BINS];         // 8 KB (used twice)
    __shared__ unsigned long long keys[CAPN];         // 32 KB
    __shared__ int s_T, s_R;
    __shared__ unsigned int s_hi, s_t, s_m;

    const int row = blockIdx.x;
    const int tid = threadIdx.x;
    float* __restrict__ o = out + (size_t)row * K_OUT;

    for (int b = tid; b < BINS; b += NT) hist[b] = 0;
    if (tid == 0) { s_T = -1; s_R = -1; s_hi = 0; s_t = 0; }
    __syncthreads();

    const uint4* __restrict__ p =
        reinterpret_cast<const uint4*>(logits + (size_t)row * ROW_N);
    const int nvec = ROW_N / 4;

    // ---- P1: primary histogram (top 11 bits of ordered key) ----
    for (int i = tid; i < nvec; i += NT) {
        uint4 v = p[i];
        atomicAdd(&hist[ord32(v.x) >> 21], 1u);
        atomicAdd(&hist[ord32(v.y) >> 21], 1u);
        atomicAdd(&hist[ord32(v.z) >> 21], 1u);
        atomicAdd(&hist[ord32(v.w) >> 21], 1u);
    }
    __syncthreads();

    // ---- P2: threshold bin T ----
    find_bin(hist, K_OUT, &s_T, tid);
    __syncthreads();
    const int Tbin = s_T;
    if (Tbin < 0) {                                   // diagnostic (impossible)
        for (int j = tid; j < K_OUT; j += NT) o[j] = 1.0e5f;
        return;
    }
    __syncthreads();
    for (int b = tid; b < BINS; b += NT) hist[b] = 0;  // reuse as refined hist
    __syncthreads();

    // ---- P3: split pass ----
    unsigned long long* __restrict__ tmp = g_tmp + (size_t)row * TCAP;
    for (int i = tid; i < nvec; i += NT) {
        uint4 v = p[i];
        unsigned int ww[4] = {v.x, v.y, v.z, v.w};
        #pragma unroll
        for (int c = 0; c < 4; c++) {
            unsigned int key = ord32(ww[c]);
            int b = (int)(key >> 21);
            if (b >= Tbin) {
                unsigned int idx = (unsigned int)(i * 4 + c);
                unsigned long long k64 = ((unsigned long long)key << 32) |
                                         (unsigned long long)(~idx);
                if (b > Tbin) {
                    unsigned int pos = atomicAdd(&s_hi, 1u);
                    if (pos < CAPN) keys[pos] = k64;
                } else {
                    unsigned int t = atomicAdd(&s_t, 1u);
                    if (t < TCAP) tmp[t] = k64;
                    atomicAdd(&hist[(key >> 10) & (BINS - 1)], 1u);
                }
            }
        }
    }
    __syncthreads();
    const unsigned int hi = s_hi;       // < K_OUT by definition of T
    const unsigned int tn = s_t;
    if (hi >= K_OUT || tn > TCAP) {     // diagnostic
        for (int j = tid; j < K_OUT; j += NT) o[j] = 9.0e4f;
        return;
    }
    if (tid == 0) s_m = hi;
    __syncthreads();

    // ---- P4: refined threshold R within bin T ----
    find_bin(hist, K_OUT - hi, &s_R, tid);
    __syncthreads();
    const int Rbin = s_R;
    if (Rbin < 0) {                     // diagnostic
        for (int j = tid; j < K_OUT; j += NT) o[j] = 1.1e5f;
        return;
    }

    // ---- P5: merge bin-T survivors (refined >= R) ----
    for (unsigned int i = tid; i < tn; i += NT) {
        unsigned long long k64 = tmp[i];
        unsigned int key = (unsigned int)(k64 >> 32);
        if ((int)((key >> 10) & (BINS - 1)) >= Rbin) {
            unsigned int pos = atomicAdd(&s_m, 1u);
            if (pos < CAPN) keys[pos] = k64;
        }
    }
    __syncthreads();
    const unsigned int m = s_m;
    if (m < K_OUT || m > CAPN) {        // diagnostic
        for (int j = tid; j < K_OUT; j += NT) o[j] = 1.2e5f;
        return;
    }
    for (unsigned int i = m + tid; i < CAPN; i += NT) keys[i] = 0ull;
    __syncthreads();

    // ---- P6: bitonic sort 4096 keys ascending (pad 0 sinks to front) ----
    for (int k2 = 2; k2 <= CAPN; k2 <<= 1) {
        for (int j2 = k2 >> 1; j2 > 0; j2 >>= 1) {
            for (int i = tid; i < CAPN; i += NT) {
                int ixj = i ^ j2;
                if (ixj > i) {
                    unsigned long long a = keys[i];
                    unsigned long long b = keys[ixj];
                    bool up = ((i & k2) == 0);
                    if (up ? (a > b) : (a < b)) { keys[i] = b; keys[ixj] = a; }
                }
            }
            __syncthreads();
        }
    }

    // ---- emit: j-th largest = keys[CAPN-1-j]; index as FLOAT32 ----
    for (int j = tid; j < K_OUT; j += NT) {
        unsigned long long k64 = keys[CAPN - 1 - j];
        unsigned int idx = ~(unsigned int)(k64 & 0xFFFFFFFFull);
        o[j] = (float)idx;              // exact: idx < 2^24
    }
}

// ---------------------------------------------------------------------------
extern "C" void kernel_launch(void* const* d_in, const int* in_sizes, int n_in,
                              void* d_out, int out_size) {
    // logits = largest input (round-9 diag: index 0, 33554432 fp32 elements)
    const float* logits = (const float*)d_in[0];
    long long best = -1;
    for (int i = 0; i < n_in; i++) {
        if ((long long)in_sizes[i] > best) {
            best = in_sizes[i];
            logits = (const float*)d_in[i];
        }
    }
    topk_kernel<<<ROWS, NT>>>(logits, (float*)d_out);
}

// round 13
// speedup vs baseline: 1.7893x; 1.7893x over previous
#include <cuda_runtime.h>
#include <cstdint>

// ---------------------------------------------------------------------------
// Per-row top-k (k=2048), 128 rows x 262144 fp32. Output: indices as float32.
//
// R12 passed at 205us but ncu showed DRAM=16%, occ=25%: the fused kernel was
// latency/atomic-paced, not bandwidth-bound. Split:
//   Kernel A: high-occupancy streaming filter (u >= 2.0f ordered) -> per-CTA
//             candidate segments. One compare/element, ~2.3% append rate.
//   Kernel B: exact top-k over the ~6K candidates per row (two-level radix
//             select + 4096-key bitonic, proven in R12). If the speculative
//             threshold under-collects (<2048) or any segment overflows,
//             falls back to the full exact R12 path over the raw row.
// Keys (ord32<<32 | ~idx): value desc, index asc ties == stable jax.lax.top_k.
// ---------------------------------------------------------------------------

#define ROWS    128
#define ROW_N   262144
#define K_OUT   2048
#define BINS    2048
#define CAPN    4096
#define NT      512

#define SUBS    8                 // collect CTAs per row
#define NTA     256               // collect threads per CTA
#define SUBCAP  2048              // per-segment cap (mean ~745, +48 sigma)
#define THETA   0xC0000000u       // ordered-uint of +2.0f
#define TCAP    8192              // fallback side-buffer per row

__device__ unsigned long long g_cand[ROWS * SUBS * SUBCAP];  // 16 MB
__device__ unsigned int       g_subcnt[ROWS * SUBS];
__device__ unsigned long long g_tmp[ROWS * TCAP];            // fallback only

static __device__ __forceinline__ unsigned int ord32(unsigned int w) {
    return (w & 0x80000000u) ? ~w : (w | 0x80000000u);
}

// warp-0 suffix-scan over hist[BINS]: find bin B with
// count(bins > B) < need <= count(bins >= B)
static __device__ __forceinline__ void find_bin(const unsigned int* hist,
                                                unsigned int need, int* outB,
                                                int tid) {
    if (tid < 32) {
        const int BPL = BINS / 32;
        unsigned int s = 0;
        for (int j = 0; j < BPL; j++) s += hist[tid * BPL + j];
        unsigned int v = s;
        #pragma unroll
        for (int d = 1; d < 32; d <<= 1) {
            unsigned int t = __shfl_down_sync(0xFFFFFFFFu, v, d);
            if (tid + d < 32) v += t;
        }
        unsigned int running = v - s;
        for (int j = BPL - 1; j >= 0; j--) {
            int b = tid * BPL + j;
            unsigned int n = hist[b];
            if (running < need && running + n >= need) *outB = b;
            running += n;
        }
    }
}

// ---------------------------------------------------------------------------
// Kernel A: streaming candidate collection. grid = ROWS*SUBS, block = NTA.
// ---------------------------------------------------------------------------
__global__ __launch_bounds__(NTA)
void collect_kernel(const float* __restrict__ logits) {
    __shared__ unsigned int s_cnt;
    const int row = blockIdx.x / SUBS;
    const int sub = blockIdx.x % SUBS;
    const int tid = threadIdx.x;
    if (tid == 0) s_cnt = 0;
    __syncthreads();

    const int CHUNK4 = ROW_N / 4 / SUBS;                 // 8192 float4
    const uint4* __restrict__ p =
        reinterpret_cast<const uint4*>(logits + (size_t)row * ROW_N) +
        sub * CHUNK4;
    unsigned long long* __restrict__ dst =
        g_cand + (size_t)blockIdx.x * SUBCAP;
    const unsigned int base = sub * (ROW_N / SUBS);      // row-local offset

    #pragma unroll 4
    for (int i = tid; i < CHUNK4; i += NTA) {
        uint4 v = p[i];
        unsigned int ww[4] = {v.x, v.y, v.z, v.w};
        #pragma unroll
        for (int c = 0; c < 4; c++) {
            unsigned int u = ord32(ww[c]);
            if (u >= THETA) {
                unsigned int pos = atomicAdd(&s_cnt, 1u);
                if (pos < SUBCAP) {
                    unsigned int idx = base + (unsigned int)(i * 4 + c);
                    dst[pos] = ((unsigned long long)u << 32) |
                               (unsigned long long)(~idx);
                }
            }
        }
    }
    __syncthreads();
    if (tid == 0) g_subcnt[blockIdx.x] = s_cnt;
}

// ---------------------------------------------------------------------------
// Kernel B: exact top-k per row from candidates (fallback: full row).
// ---------------------------------------------------------------------------
__global__ __launch_bounds__(NT, 1)
void select_kernel(const float* __restrict__ logits, float* __restrict__ out) {
    __shared__ unsigned int       hist[BINS];            // 8 KB (used twice)
    __shared__ unsigned long long keys[CAPN];            // 32 KB
    __shared__ unsigned int       sc[SUBS];
    __shared__ int s_T, s_R, s_fb;
    __shared__ unsigned int s_hi, s_m;

    const int row = blockIdx.x;
    const int tid = threadIdx.x;
    float* __restrict__ o = out + (size_t)row * K_OUT;

    if (tid < SUBS) sc[tid] = g_subcnt[row * SUBS + tid];
    for (int b = tid; b < BINS; b += NT) hist[b] = 0;
    if (tid == 0) { s_T = -1; s_R = -1; s_hi = 0; }
    __syncthreads();
    if (tid == 0) {
        unsigned int total = 0; int bad = 0;
        for (int s = 0; s < SUBS; s++) {
            if (sc[s] > SUBCAP) bad = 1;
            total += sc[s];
        }
        if (total < K_OUT) bad = 1;   // speculative threshold under-collected
        s_fb = bad;
    }
    __syncthreads();

    const unsigned long long* __restrict__ cb =
        g_cand + (size_t)row * SUBS * SUBCAP;

    if (!s_fb) {
        // ================= sparse path (candidates only) ==================
        // P1: histogram of candidate key top-11 bits
        for (int seg = 0; seg < SUBS; seg++) {
            const unsigned int n = sc[seg];
            for (unsigned int i = tid; i < n; i += NT) {
                unsigned int key = (unsigned int)(cb[seg * SUBCAP + i] >> 32);
                atomicAdd(&hist[key >> 21], 1u);
            }
        }
        __syncthreads();
        find_bin(hist, K_OUT, &s_T, tid);
        __syncthreads();
        const int Tb = s_T;
        __syncthreads();
        for (int b = tid; b < BINS; b += NT) hist[b] = 0;
        __syncthreads();

        // P3: bins>T -> keys; bin==T -> refined histogram
        for (int seg = 0; seg < SUBS; seg++) {
            const unsigned int n = sc[seg];
            for (unsigned int i = tid; i < n; i += NT) {
                unsigned long long k64 = cb[seg * SUBCAP + i];
                unsigned int key = (unsigned int)(k64 >> 32);
                int b = (int)(key >> 21);
                if (b > Tb) {
                    unsigned int pos = atomicAdd(&s_hi, 1u);
                    if (pos < CAPN) keys[pos] = k64;
                } else if (b == Tb) {
                    atomicAdd(&hist[(key >> 10) & (BINS - 1)], 1u);
                }
            }
        }
        __syncthreads();
        const unsigned int hi = s_hi;
        if (tid == 0) s_m = hi;
        __syncthreads();
        find_bin(hist, K_OUT - hi, &s_R, tid);
        __syncthreads();
        const int Rb = s_R;

        // P5: merge bin-T survivors (refined >= R)
        for (int seg = 0; seg < SUBS; seg++) {
            const unsigned int n = sc[seg];
            for (unsigned int i = tid; i < n; i += NT) {
                unsigned long long k64 = cb[seg * SUBCAP + i];
                unsigned int key = (unsigned int)(k64 >> 32);
                if ((int)(key >> 21) == Tb &&
                    (int)((key >> 10) & (BINS - 1)) >= Rb) {
                    unsigned int pos = atomicAdd(&s_m, 1u);
                    if (pos < CAPN) keys[pos] = k64;
                }
            }
        }
        __syncthreads();
        const unsigned int m = s_m;
        if (m < K_OUT || m > CAPN) {               // should be impossible
            for (int j = tid; j < K_OUT; j += NT) o[j] = 1.2e5f;
            return;
        }
        for (unsigned int i = m + tid; i < CAPN; i += NT) keys[i] = 0ull;
        __syncthreads();
    } else {
        // ================= fallback: full exact R12 path ===================
        const uint4* __restrict__ p =
            reinterpret_cast<const uint4*>(logits + (size_t)row * ROW_N);
        const int nvec = ROW_N / 4;

        for (int i = tid; i < nvec; i += NT) {
            uint4 v = p[i];
            atomicAdd(&hist[ord32(v.x) >> 21], 1u);
            atomicAdd(&hist[ord32(v.y) >> 21], 1u);
            atomicAdd(&hist[ord32(v.z) >> 21], 1u);
            atomicAdd(&hist[ord32(v.w) >> 21], 1u);
        }
        __syncthreads();
        find_bin(hist, K_OUT, &s_T, tid);
        __syncthreads();
        const int Tb = s_T;
        __syncthreads();
        for (int b = tid; b < BINS; b += NT) hist[b] = 0;
        if (tid == 0) s_hi = 0;
        __syncthreads();

        __shared__ unsigned int s_t;
        if (tid == 0) s_t = 0;
        __syncthreads();
        unsigned long long* __restrict__ tmp = g_tmp + (size_t)row * TCAP;
        for (int i = tid; i < nvec; i += NT) {
            uint4 v = p[i];
            unsigned int ww[4] = {v.x, v.y, v.z, v.w};
            #pragma unroll
            for (int c = 0; c < 4; c++) {
                unsigned int key = ord32(ww[c]);
                int b = (int)(key >> 21);
                if (b >= Tb) {
                    unsigned int idx = (unsigned int)(i * 4 + c);
                    unsigned long long k64 = ((unsigned long long)key << 32) |
                                             (unsigned long long)(~idx);
                    if (b > Tb) {
                        unsigned int pos = atomicAdd(&s_hi, 1u);
                        if (pos < CAPN) keys[pos] = k64;
                    } else {
                        unsigned int t = atomicAdd(&s_t, 1u);
                        if (t < TCAP) tmp[t] = k64;
                        atomicAdd(&hist[(key >> 10) & (BINS - 1)], 1u);
                    }
                }
            }
        }
        __syncthreads();
        const unsigned int hi = s_hi;
        const unsigned int tn = s_t;
        if (hi >= K_OUT || tn > TCAP) {
            for (int j = tid; j < K_OUT; j += NT) o[j] = 9.0e4f;
            return;
        }
        if (tid == 0) s_m = hi;
        __syncthreads();
        find_bin(hist, K_OUT - hi, &s_R, tid);
        __syncthreads();
        const int Rb = s_R;
        for (unsigned int i = tid; i < tn; i += NT) {
            unsigned long long k64 = tmp[i];
            unsigned int key = (unsigned int)(k64 >> 32);
            if ((int)((key >> 10) & (BINS - 1)) >= Rb) {
                unsigned int pos = atomicAdd(&s_m, 1u);
                if (pos < CAPN) keys[pos] = k64;
            }
        }
        __syncthreads();
        const unsigned int m = s_m;
        if (m < K_OUT || m > CAPN) {
            for (int j = tid; j < K_OUT; j += NT) o[j] = 1.2e5f;
            return;
        }
        for (unsigned int i = m + tid; i < CAPN; i += NT) keys[i] = 0ull;
        __syncthreads();
    }

    // ---- bitonic sort 4096 keys ascending (pad 0 sinks to front) ----
    for (int k2 = 2; k2 <= CAPN; k2 <<= 1) {
        for (int j2 = k2 >> 1; j2 > 0; j2 >>= 1) {
            for (int i = tid; i < CAPN; i += NT) {
                int ixj = i ^ j2;
                if (ixj > i) {
                    unsigned long long a = keys[i];
                    unsigned long long b = keys[ixj];
                    bool up = ((i & k2) == 0);
                    if (up ? (a > b) : (a < b)) { keys[i] = b; keys[ixj] = a; }
                }
            }
            __syncthreads();
        }
    }

    // ---- emit: j-th largest = keys[CAPN-1-j]; index as float32 (exact) ----
    for (int j = tid; j < K_OUT; j += NT) {
        unsigned long long k64 = keys[CAPN - 1 - j];
        unsigned int idx = ~(unsigned int)(k64 & 0xFFFFFFFFull);
        o[j] = (float)idx;
    }
}

// ---------------------------------------------------------------------------
extern "C" void kernel_launch(void* const* d_in, const int* in_sizes, int n_in,
                              void* d_out, int out_size) {
    const float* logits = (const float*)d_in[0];
    long long best = -1;
    for (int i = 0; i < n_in; i++) {
        if ((long long)in_sizes[i] > best) {
            best = in_sizes[i];
            logits = (const float*)d_in[i];
        }
    }
    collect_kernel<<<ROWS * SUBS, NTA>>>(logits);
    select_kernel<<<ROWS, NT>>>(logits, (float*)d_out);
}

// round 14
// speedup vs baseline: 2.2167x; 1.2389x over previous
#include <cuda_runtime.h>
#include <cstdint>

// ---------------------------------------------------------------------------
// Per-row top-k (k=2048), 128 rows x 262144 fp32. Output: indices as float32.
//
// R13: collect ~31.6us (4 TB/s, fine), select 83us (bitonic latency-bound).
// This round replaces the 78-stage bitonic with a counting sort:
//   select:  primary hist -> Tb (+count above), refined hist -> Rb
//            => survivor predicate collapses to  u >= uthr = (Tb<<21)|(Rb<<10)
//            fine monotone bins fbin = (u-uthr)*4096/range  (~3 keys max/bin)
//            warp suffix-scan -> packed (beg<<16 | cursor) -> scatter ->
//            per-bin insertion sort on full 64-bit keys -> emit.
// Keys (ord32<<32 | ~idx): value desc, index asc ties == stable jax.lax.top_k.
// Fallback (speculative threshold under-collects / segment overflow): same
// passes over the raw row (exact; never taken for this data).
// ---------------------------------------------------------------------------

#define ROWS    128
#define ROW_N   262144
#define K_OUT   2048
#define PBINS   2048              // primary/refined bins (11 bits)
#define FBINS   4096              // fine counting-sort bins
#define SCAP    3072              // scatter capacity (m ~ 2050-2100)
#define NT      512

#define SUBS    16                // collect CTAs per row
#define NTA     256               // collect threads per CTA
#define SUBCAP  1024              // per-segment cap (mean ~373, +34 sigma)
#define THETA   0xC0000000u       // ordered-uint of +2.0f

__device__ unsigned long long g_cand[ROWS * SUBS * SUBCAP];  // 16 MB
__device__ unsigned int       g_subcnt[ROWS * SUBS];

static __device__ __forceinline__ unsigned int ord32(unsigned int w) {
    return (w & 0x80000000u) ? ~w : (w | 0x80000000u);
}

// warp-0 suffix-scan over hist[nbins]: find bin B with
// above(B) < need <= above(B)+hist[B]; outAbove = count in bins > B.
static __device__ __forceinline__ void find_bin(const unsigned int* hist,
                                                int nbins, unsigned int need,
                                                int* outB, unsigned int* outAbove,
                                                int tid) {
    if (tid < 32) {
        const int BPL = nbins / 32;
        unsigned int s = 0;
        for (int j = 0; j < BPL; j++) s += hist[tid * BPL + j];
        unsigned int v = s;
        #pragma unroll
        for (int d = 1; d < 32; d <<= 1) {
            unsigned int t = __shfl_down_sync(0xFFFFFFFFu, v, d);
            if (tid + d < 32) v += t;
        }
        unsigned int running = v - s;
        for (int j = BPL - 1; j >= 0; j--) {
            int b = tid * BPL + j;
            unsigned int n = hist[b];
            if (running < need && running + n >= need) {
                *outB = b;
                *outAbove = running;
            }
            running += n;
        }
    }
}

// ---------------------------------------------------------------------------
// Kernel A: streaming candidate collection. grid = ROWS*SUBS, block = NTA.
// ---------------------------------------------------------------------------
__global__ __launch_bounds__(NTA)
void collect_kernel(const float* __restrict__ logits) {
    __shared__ unsigned int s_cnt;
    const int row = blockIdx.x / SUBS;
    const int sub = blockIdx.x % SUBS;
    const int tid = threadIdx.x;
    if (tid == 0) s_cnt = 0;
    __syncthreads();

    const int CHUNK4 = ROW_N / 4 / SUBS;                 // 4096 uint4
    const uint4* __restrict__ p =
        reinterpret_cast<const uint4*>(logits + (size_t)row * ROW_N) +
        sub * CHUNK4;
    unsigned long long* __restrict__ dst =
        g_cand + (size_t)blockIdx.x * SUBCAP;
    const unsigned int base = sub * (ROW_N / SUBS);

    #pragma unroll 4
    for (int i = tid; i < CHUNK4; i += NTA) {
        uint4 v = p[i];
        unsigned int ww[4] = {v.x, v.y, v.z, v.w};
        #pragma unroll
        for (int c = 0; c < 4; c++) {
            unsigned int u = ord32(ww[c]);
            if (u >= THETA) {
                unsigned int pos = atomicAdd(&s_cnt, 1u);
                if (pos < SUBCAP) {
                    unsigned int idx = base + (unsigned int)(i * 4 + c);
                    dst[pos] = ((unsigned long long)u << 32) |
                               (unsigned long long)(~idx);
                }
            }
        }
    }
    __syncthreads();
    if (tid == 0) g_subcnt[blockIdx.x] = s_cnt;
}

// ---------------------------------------------------------------------------
// Kernel B: exact top-k per row. Counting-sort finish (no bitonic).
// ---------------------------------------------------------------------------
__global__ __launch_bounds__(NT, 1)
void select_kernel(const float* __restrict__ logits, float* __restrict__ out) {
    __shared__ unsigned int       fb[FBINS];     // 16 KB (hists, then cursors)
    __shared__ unsigned long long sorted[SCAP];  // 24 KB
    __shared__ unsigned int       sc[SUBS];
    __shared__ int s_T, s_R, s_fb;
    __shared__ unsigned int s_hi, s_m, s_umax;

    const int row = blockIdx.x;
    const int tid = threadIdx.x;
    float* __restrict__ o = out + (size_t)row * K_OUT;
    const unsigned long long* __restrict__ cb =
        g_cand + (size_t)row * SUBS * SUBCAP;
    const unsigned int* __restrict__ rowbits =
        reinterpret_cast<const unsigned int*>(logits + (size_t)row * ROW_N);

    if (tid < SUBS) sc[tid] = g_subcnt[row * SUBS + tid];
    for (int b = tid; b < PBINS; b += NT) fb[b] = 0;
    if (tid == 0) { s_T = -1; s_R = -1; s_hi = 0; s_umax = 0; }
    __syncthreads();
    if (tid == 0) {
        unsigned int total = 0; int bad = 0;
        for (int s = 0; s < SUBS; s++) {
            if (sc[s] > SUBCAP) bad = 1;
            total += sc[s];
        }
        if (total < K_OUT) bad = 1;
        s_fb = bad;
    }
    __syncthreads();
    const int fbk = s_fb;

    // ---- P1: primary histogram (top 11 bits) + umax ----
    if (!fbk) {
        for (int seg = 0; seg < SUBS; seg++) {
            const unsigned long long* s = cb + seg * SUBCAP;
            const unsigned int n = sc[seg];
            for (unsigned int i = tid; i < n; i += NT) {
                unsigned int u = (unsigned int)(s[i] >> 32);
                atomicAdd(&fb[u >> 21], 1u);
                atomicMax(&s_umax, u);
            }
        }
    } else {
        for (int i = tid; i < ROW_N; i += NT) {
            unsigned int u = ord32(rowbits[i]);
            atomicAdd(&fb[u >> 21], 1u);
            atomicMax(&s_umax, u);
        }
    }
    __syncthreads();

    // ---- P2: threshold bin Tb (+ count above = hi) ----
    find_bin(fb, PBINS, K_OUT, &s_T, &s_hi, tid);
    __syncthreads();
    const int Tb = s_T;
    const unsigned int hi = s_hi;
    const unsigned int umax = s_umax;
    __syncthreads();
    for (int b = tid; b < PBINS; b += NT) fb[b] = 0;
    __syncthreads();

    // ---- P3: refined histogram within bin Tb (bits [10,21)) ----
    if (!fbk) {
        for (int seg = 0; seg < SUBS; seg++) {
            const unsigned long long* s = cb + seg * SUBCAP;
            const unsigned int n = sc[seg];
            for (unsigned int i = tid; i < n; i += NT) {
                unsigned int u = (unsigned int)(s[i] >> 32);
                if ((int)(u >> 21) == Tb)
                    atomicAdd(&fb[(u >> 10) & (PBINS - 1)], 1u);
            }
        }
    } else {
        for (int i = tid; i < ROW_N; i += NT) {
            unsigned int u = ord32(rowbits[i]);
            if ((int)(u >> 21) == Tb)
                atomicAdd(&fb[(u >> 10) & (PBINS - 1)], 1u);
        }
    }
    __syncthreads();

    // ---- P4: refined threshold Rb ----
    {
        __shared__ unsigned int dummy;
        find_bin(fb, PBINS, K_OUT - hi, &s_R, &dummy, tid);
    }
    __syncthreads();
    const int Rb = s_R;
    const unsigned int uthr = ((unsigned int)Tb << 21) | ((unsigned int)Rb << 10);
    const unsigned long long range = (unsigned long long)(umax - uthr) + 1ull;
    __syncthreads();
    for (int b = tid; b < FBINS; b += NT) fb[b] = 0;
    __syncthreads();

    // ---- P5: fine histogram of survivors (u >= uthr), monotone bins ----
    if (!fbk) {
        for (int seg = 0; seg < SUBS; seg++) {
            const unsigned long long* s = cb + seg * SUBCAP;
            const unsigned int n = sc[seg];
            for (unsigned int i = tid; i < n; i += NT) {
                unsigned int u = (unsigned int)(s[i] >> 32);
                if (u >= uthr) {
                    unsigned int fbin = (unsigned int)
                        (((unsigned long long)(u - uthr) * FBINS) / range);
                    atomicAdd(&fb[fbin], 1u);
                }
            }
        }
    } else {
        for (int i = tid; i < ROW_N; i += NT) {
            unsigned int u = ord32(rowbits[i]);
            if (u >= uthr) {
                unsigned int fbin = (unsigned int)
                    (((unsigned long long)(u - uthr) * FBINS) / range);
                atomicAdd(&fb[fbin], 1u);
            }
        }
    }
    __syncthreads();

    // ---- P6: descending offsets; pack (beg<<16)|cursor; total -> s_m ----
    if (tid < 32) {
        const int BPL = FBINS / 32;                  // 128 bins per lane
        unsigned int s = 0;
        for (int j = 0; j < BPL; j++) s += fb[tid * BPL + j];
        unsigned int v = s;
        #pragma unroll
        for (int d = 1; d < 32; d <<= 1) {
            unsigned int t = __shfl_down_sync(0xFFFFFFFFu, v, d);
            if (tid + d < 32) v += t;
        }
        if (tid == 0) s_m = v;                       // total survivors
        unsigned int running = v - s;                // count of bins above
        for (int j = BPL - 1; j >= 0; j--) {
            int b = tid * BPL + j;
            unsigned int n = fb[b];
            fb[b] = (running << 16) | running;       // beg | cursor
            running += n;
        }
    }
    __syncthreads();
    const unsigned int m = s_m;
    if (m < K_OUT || m > SCAP) {                     // loud fail (never taken)
        for (int j = tid; j < K_OUT; j += NT) o[j] = 1.2e5f;
        return;
    }

    // ---- P7: scatter survivors into fine-bin order ----
    if (!fbk) {
        for (int seg = 0; seg < SUBS; seg++) {
            const unsigned long long* s = cb + seg * SUBCAP;
            const unsigned int n = sc[seg];
            for (unsigned int i = tid; i < n; i += NT) {
                unsigned long long k64 = s[i];
                unsigned int u = (unsigned int)(k64 >> 32);
                if (u >= uthr) {
                    unsigned int fbin = (unsigned int)
                        (((unsigned long long)(u - uthr) * FBINS) / range);
                    unsigned int pos = atomicAdd(&fb[fbin], 1u) & 0xFFFFu;
                    if (pos < SCAP) sorted[pos] = k64;
                }
            }
        }
    } else {
        for (int i = tid; i < ROW_N; i += NT) {
            unsigned int u = ord32(rowbits[i]);
            if (u >= uthr) {
                unsigned int fbin = (unsigned int)
                    (((unsigned long long)(u - uthr) * FBINS) / range);
                unsigned int pos = atomicAdd(&fb[fbin], 1u) & 0xFFFFu;
                if (pos < SCAP) {
                    sorted[pos] = ((unsigned long long)u << 32) |
                                  (unsigned long long)(~(unsigned int)i);
                }
            }
        }
    }
    __syncthreads();

    // ---- P8: per-bin insertion sort (descending by full unique key) ----
    for (int b = tid; b < FBINS; b += NT) {
        unsigned int w = fb[b];
        int s = (int)(w >> 16);
        if (s >= K_OUT) continue;                    // bin entirely past k
        int e = (int)(w & 0xFFFFu);
        if (e > SCAP) e = SCAP;
        for (int x = s + 1; x < e; x++) {
            unsigned long long v = sorted[x];
            int y = x - 1;
            while (y >= s && sorted[y] < v) { sorted[y + 1] = sorted[y]; y--; }
            sorted[y + 1] = v;
        }
    }
    __syncthreads();

    // ---- emit: position j is the j-th largest; index as float32 (exact) ----
    for (int j = tid; j < K_OUT; j += NT) {
        unsigned int idx = ~(unsigned int)(sorted[j] & 0xFFFFFFFFull);
        o[j] = (float)idx;
    }
}

// ---------------------------------------------------------------------------
extern "C" void kernel_launch(void* const* d_in, const int* in_sizes, int n_in,
                              void* d_out, int out_size) {
    const float* logits = (const float*)d_in[0];
    long long best = -1;
    for (int i = 0; i < n_in; i++) {
        if ((long long)in_sizes[i] > best) {
            best = in_sizes[i];
            logits = (const float*)d_in[i];
        }
    }
    collect_kernel<<<ROWS * SUBS, NTA>>>(logits);
    select_kernel<<<ROWS, NT>>>(logits, (float*)d_out);
}

// round 16
// speedup vs baseline: 2.7093x; 1.2222x over previous
#include <cuda_runtime.h>
#include <cstdint>

// ---------------------------------------------------------------------------
// Per-row top-k (k=2048), 128 rows x 262144 fp32. Output: indices as float32.
//
// (Round 15: GB300 container failed twice -- infra, not kernel. Resubmitting
//  the round-14 candidate unchanged to keep the experiment controlled.)
//
// R14: select was 60us -- paced by 16 sequential tiny per-segment loops
// (~80 exposed global-latency round trips). Fix:
//   collect: warp-ballot smem staging, ONE global atomic per CTA -> dense
//            per-row candidate array g_cand[row*CAP .. +n).
//   select:  all candidates have u >= THETA, so counting-sort them directly:
//            fine monotone bins (u-THETA)>>12 (4096 bins over [2.0,8.0)),
//            warp suffix-scan -> (beg<<16|cursor), scatter, per-bin insertion
//            sort on unique 64-bit keys, emit first 2048.
// Keys (ord32<<32 | ~idx): value desc, index asc ties == stable jax.lax.top_k.
// Fallback (undercollect/overflow/straddle): exact full-row two-level radix
// select + fine counting sort (R14's proven path). Never taken for N(0,1).
// ---------------------------------------------------------------------------

#define ROWS    128
#define ROW_N   262144
#define K_OUT   2048
#define PBINS   2048              // fallback primary/refined bins
#define FBINS   4096              // fine counting-sort bins
#define SCAP    3072              // scatter capacity
#define NT      512

#define SUBS    16                // collect CTAs per row
#define NTA     256               // collect threads per CTA
#define SUBCAP  1024              // per-CTA stage cap (mean ~373, +34 sigma)
#define CAP     (SUBS * SUBCAP)   // per-row candidate cap = 16384
#define THETA   0xC0000000u       // ordered-uint of +2.0f

__device__ unsigned long long g_cand[ROWS * CAP];   // 16 MB
__device__ unsigned int       g_cnt[ROWS];

static __device__ __forceinline__ unsigned int ord32(unsigned int w) {
    return (w & 0x80000000u) ? ~w : (w | 0x80000000u);
}

// warp-0 suffix-scan over hist[nbins]: find bin B with
// above(B) < need <= above(B)+hist[B]; outAbove = count in bins > B.
static __device__ __forceinline__ void find_bin(const unsigned int* hist,
                                                int nbins, unsigned int need,
                                                int* outB, unsigned int* outAbove,
                                                int tid) {
    if (tid < 32) {
        const int BPL = nbins / 32;
        unsigned int s = 0;
        for (int j = 0; j < BPL; j++) s += hist[tid * BPL + j];
        unsigned int v = s;
        #pragma unroll
        for (int d = 1; d < 32; d <<= 1) {
            unsigned int t = __shfl_down_sync(0xFFFFFFFFu, v, d);
            if (tid + d < 32) v += t;
        }
        unsigned int running = v - s;
        for (int j = BPL - 1; j >= 0; j--) {
            int b = tid * BPL + j;
            unsigned int n = hist[b];
            if (running < need && running + n >= need) {
                *outB = b;
                *outAbove = running;
            }
            running += n;
        }
    }
}

// warp-0 suffix-scan over fb[FBINS]: fb[b] := (beg<<16)|beg where beg =
// count of keys in bins > b. *outTotal = grand total. *outBad |= 1 if any
// bin with beg < K_OUT would scatter past SCAP.
static __device__ __forceinline__ void scan_pack(unsigned int* fbx,
                                                 unsigned int* outTotal,
                                                 int* outBad, int tid) {
    if (tid < 32) {
        const int BPL = FBINS / 32;                  // 128 bins per lane
        unsigned int s = 0;
        for (int j = 0; j < BPL; j++) s += fbx[tid * BPL + j];
        unsigned int v = s;
        #pragma unroll
        for (int d = 1; d < 32; d <<= 1) {
            unsigned int t = __shfl_down_sync(0xFFFFFFFFu, v, d);
            if (tid + d < 32) v += t;
        }
        if (tid == 0) *outTotal = v;
        unsigned int running = v - s;
        for (int j = BPL - 1; j >= 0; j--) {
            int b = tid * BPL + j;
            unsigned int n = fbx[b];
            if (running < K_OUT && running + n > SCAP) *outBad = 1;
            fbx[b] = (running << 16) | running;      // beg | cursor
            running += n;
        }
    }
}

// ---------------------------------------------------------------------------
// Kernel A: streaming collect -> dense per-row candidate array.
// ---------------------------------------------------------------------------
__global__ __launch_bounds__(NTA)
void collect_kernel(const float* __restrict__ logits) {
    __shared__ unsigned long long stage[SUBCAP];     // 8 KB
    __shared__ unsigned int s_cnt, s_base;

    const int row  = blockIdx.x / SUBS;
    const int sub  = blockIdx.x % SUBS;
    const int tid  = threadIdx.x;
    const int lane = tid & 31;
    const unsigned int ltmask = (1u << lane) - 1u;

    if (tid == 0) s_cnt = 0;
    __syncthreads();

    const int CHUNK4 = ROW_N / 4 / SUBS;             // 4096 uint4 (16 iters)
    const uint4* __restrict__ p =
        reinterpret_cast<const uint4*>(logits + (size_t)row * ROW_N) +
        sub * CHUNK4;
    const unsigned int base_idx = sub * (ROW_N / SUBS);

    for (int i = tid; i < CHUNK4; i += NTA) {        // uniform trip count
        uint4 v = p[i];
        unsigned int ww[4] = {v.x, v.y, v.z, v.w};
        #pragma unroll
        for (int c = 0; c < 4; c++) {
            unsigned int u = ord32(ww[c]);
            bool pred = (u >= THETA);
            unsigned int mask = __ballot_sync(0xFFFFFFFFu, pred);
            if (mask) {
                int leader = __ffs(mask) - 1;
                unsigned int bp = 0;
                if (lane == leader)
                    bp = atomicAdd(&s_cnt, (unsigned int)__popc(mask));
                bp = __shfl_sync(0xFFFFFFFFu, bp, leader);
                if (pred) {
                    unsigned int pos = bp + __popc(mask & ltmask);
                    if (pos < SUBCAP) {
                        unsigned int idx = base_idx + (unsigned int)(i * 4 + c);
                        stage[pos] = ((unsigned long long)u << 32) |
                                     (unsigned long long)(~idx);
                    }
                }
            }
        }
    }
    __syncthreads();

    if (tid == 0) {
        unsigned int cnt = s_cnt;
        unsigned int add = (cnt > SUBCAP) ? (SUBCAP + 0x40000u) : cnt;
        // overflow poisons the row count -> n > CAP -> exact fallback
        s_base = atomicAdd(&g_cnt[row], add);
        s_cnt = (cnt > SUBCAP) ? SUBCAP : cnt;
    }
    __syncthreads();

    const unsigned int cnt = s_cnt;
    const unsigned int base = s_base & 0x3FFFFu;     // strip any poison bits
    unsigned long long* __restrict__ dst = g_cand + (size_t)row * CAP;
    for (unsigned int i = tid; i < cnt && base + i < CAP; i += NTA)
        dst[base + i] = stage[i];
}

// ---------------------------------------------------------------------------
// Kernel B: per-row counting-sort of candidates -> top-2048 indices.
// ---------------------------------------------------------------------------
__global__ __launch_bounds__(NT, 1)
void select_kernel(const float* __restrict__ logits, float* __restrict__ out) {
    __shared__ unsigned int       fb[FBINS];         // 16 KB
    __shared__ unsigned long long sorted[SCAP];      // 24 KB
    __shared__ int s_bad, s_T, s_R;
    __shared__ unsigned int s_m, s_hi, s_umax, s_dummy;

    const int row = blockIdx.x;
    const int tid = threadIdx.x;
    float* __restrict__ o = out + (size_t)row * K_OUT;
    const unsigned long long* __restrict__ cb = g_cand + (size_t)row * CAP;
    const unsigned int* __restrict__ rowbits =
        reinterpret_cast<const unsigned int*>(logits + (size_t)row * ROW_N);

    const unsigned int n = g_cnt[row];
    const bool good = (n >= K_OUT && n <= CAP);

    if (tid == 0) s_bad = good ? 0 : 1;
    for (int b = tid; b < FBINS; b += NT) fb[b] = 0;
    __syncthreads();

    if (!s_bad) {
        // ============ good path: counting-sort ALL candidates ============
        // pass 1: fine histogram (monotone bins over [2.0, 8.0))
        for (unsigned int i = tid; i < n; i += NT) {
            unsigned int u = (unsigned int)(cb[i] >> 32);
            unsigned int fbin = (u - THETA) >> 12;
            if (fbin > FBINS - 1) fbin = FBINS - 1;
            atomicAdd(&fb[fbin], 1u);
        }
        __syncthreads();

        scan_pack(fb, &s_m, &s_bad, tid);
        __syncthreads();

        if (!s_bad) {
            // pass 2: scatter
            for (unsigned int i = tid; i < n; i += NT) {
                unsigned long long k64 = cb[i];
                unsigned int u = (unsigned int)(k64 >> 32);
                unsigned int fbin = (u - THETA) >> 12;
                if (fbin > FBINS - 1) fbin = FBINS - 1;
                unsigned int pos = atomicAdd(&fb[fbin], 1u) & 0xFFFFu;
                if (pos < SCAP) sorted[pos] = k64;
            }
            __syncthreads();

            // per-bin insertion sort (descending by full unique key)
            for (int b = tid; b < FBINS; b += NT) {
                unsigned int w = fb[b];
                int s = (int)(w >> 16);
                if (s >= K_OUT) continue;
                int e = (int)(w & 0xFFFFu);
                if (e > SCAP) e = SCAP;
                for (int x = s + 1; x < e; x++) {
                    unsigned long long v = sorted[x];
                    int y = x - 1;
                    while (y >= s && sorted[y] < v) {
                        sorted[y + 1] = sorted[y]; y--;
                    }
                    sorted[y + 1] = v;
                }
            }
            __syncthreads();

            for (int j = tid; j < K_OUT; j += NT) {
                unsigned int idx = ~(unsigned int)(sorted[j] & 0xFFFFFFFFull);
                o[j] = (float)idx;
            }
            return;
        }
    }
    __syncthreads();

    // ============ exact full-row fallback (two-level + fine) ============
    for (int b = tid; b < FBINS; b += NT) fb[b] = 0;
    if (tid == 0) { s_T = -1; s_R = -1; s_hi = 0; s_umax = 0; }
    __syncthreads();

    // P1: primary histogram (top 11 bits) + umax
    for (int i = tid; i < ROW_N; i += NT) {
        unsigned int u = ord32(rowbits[i]);
        atomicAdd(&fb[u >> 21], 1u);
        atomicMax(&s_umax, u);
    }
    __syncthreads();
    find_bin(fb, PBINS, K_OUT, &s_T, &s_hi, tid);
    __syncthreads();
    const int Tb = s_T;
    const unsigned int hi = s_hi;
    const unsigned int umax = s_umax;
    __syncthreads();
    for (int b = tid; b < FBINS; b += NT) fb[b] = 0;
    __syncthreads();

    // P3: refined histogram within bin Tb
    for (int i = tid; i < ROW_N; i += NT) {
        unsigned int u = ord32(rowbits[i]);
        if ((int)(u >> 21) == Tb)
            atomicAdd(&fb[(u >> 10) & (PBINS - 1)], 1u);
    }
    __syncthreads();
    find_bin(fb, PBINS, K_OUT - hi, &s_R, &s_dummy, tid);
    __syncthreads();
    const int Rb = s_R;
    const unsigned int uthr = ((unsigned int)Tb << 21) | ((unsigned int)Rb << 10);
    const unsigned long long range = (unsigned long long)(umax - uthr) + 1ull;
    __syncthreads();
    for (int b = tid; b < FBINS; b += NT) fb[b] = 0;
    if (tid == 0) s_bad = 0;
    __syncthreads();

    // P5: fine histogram of survivors (u >= uthr)
    for (int i = tid; i < ROW_N; i += NT) {
        unsigned int u = ord32(rowbits[i]);
        if (u >= uthr) {
            unsigned int fbin = (unsigned int)
                (((unsigned long long)(u - uthr) * FBINS) / range);
            atomicAdd(&fb[fbin], 1u);
        }
    }
    __syncthreads();
    scan_pack(fb, &s_m, &s_bad, tid);
    __syncthreads();
    const unsigned int m = s_m;
    if (m < K_OUT || m > SCAP || s_bad) {    // loud fail (degenerate dups)
        for (int j = tid; j < K_OUT; j += NT) o[j] = 1.2e5f;
        return;
    }

    // P7: scatter survivors from the raw row
    for (int i = tid; i < ROW_N; i += NT) {
        unsigned int u = ord32(rowbits[i]);
        if (u >= uthr) {
            unsigned int fbin = (unsigned int)
                (((unsigned long long)(u - uthr) * FBINS) / range);
            unsigned int pos = atomicAdd(&fb[fbin], 1u) & 0xFFFFu;
            if (pos < SCAP) {
                sorted[pos] = ((unsigned long long)u << 32) |
                              (unsigned long long)(~(unsigned int)i);
            }
        }
    }
    __syncthreads();

    // P8: per-bin insertion sort
    for (int b = tid; b < FBINS; b += NT) {
        unsigned int w = fb[b];
        int s = (int)(w >> 16);
        if (s >= K_OUT) continue;
        int e = (int)(w & 0xFFFFu);
        if (e > SCAP) e = SCAP;
        for (int x = s + 1; x < e; x++) {
            unsigned long long v = sorted[x];
            int y = x - 1;
            while (y >= s && sorted[y] < v) { sorted[y + 1] = sorted[y]; y--; }
            sorted[y + 1] = v;
        }
    }
    __syncthreads();

    for (int j = tid; j < K_OUT; j += NT) {
        unsigned int idx = ~(unsigned int)(sorted[j] & 0xFFFFFFFFull);
        o[j] = (float)idx;
    }
}

// ---------------------------------------------------------------------------
extern "C" void kernel_launch(void* const* d_in, const int* in_sizes, int n_in,
                              void* d_out, int out_size) {
    const float* logits = (const float*)d_in[0];
    long long best = -1;
    for (int i = 0; i < n_in; i++) {
        if ((long long)in_sizes[i] > best) {
            best = in_sizes[i];
            logits = (const float*)d_in[i];
        }
    }
    void* cnt_ptr = nullptr;
    cudaGetSymbolAddress(&cnt_ptr, g_cnt);
    cudaMemsetAsync(cnt_ptr, 0, ROWS * sizeof(unsigned int), 0);
    collect_kernel<<<ROWS * SUBS, NTA>>>(logits);
    select_kernel<<<ROWS, NT>>>(logits, (float*)d_out);
}

// round 17
// speedup vs baseline: 4.0006x; 1.4766x over previous
#include <cuda_runtime.h>
#include <cstdint>

// ---------------------------------------------------------------------------
// Per-row top-k (k=2048), 128 rows x 262144 fp32. Output: indices as float32.
//
// R16: collect ~47us (ballot convergence killed MLP), select 26us (serial
// single-warp scan + 6K candidates). Fixes:
//   collect: direct predicated smem append (no ballot; hits ~1.2% at theta=2.25
//            so smem atomic traffic is negligible), unrolled uint4 loads.
//   select:  ~3.2K candidates, NT=1024, block-parallel suffix scan.
// Keys (ord32<<32 | ~idx): value desc, index asc ties == stable jax.lax.top_k.
// Fallback (undercollect/overflow/straddle): exact full-row two-level radix
// select + fine counting sort. Never taken for N(0,1).
// ---------------------------------------------------------------------------

#define ROWS    128
#define ROW_N   262144
#define K_OUT   2048
#define PBINS   2048              // fallback primary/refined bins
#define FBINS   4096              // fine counting-sort bins
#define SCAP    3072              // scatter capacity
#define NT      1024              // select threads
#define BPT     (FBINS / NT)      // bins per thread in scan = 4

#define SUBS    16                // collect CTAs per row
#define NTA     256               // collect threads per CTA
#define SUBCAP  512               // per-CTA stage cap (mean ~200, +22 sigma)
#define CAP     (SUBS * SUBCAP)   // per-row candidate cap = 8192
#define THETA   0xC0100000u       // ordered-uint of +2.25f

__device__ unsigned long long g_cand[ROWS * CAP];   // 8 MB
__device__ unsigned int       g_cnt[ROWS];

static __device__ __forceinline__ unsigned int ord32(unsigned int w) {
    return (w & 0x80000000u) ? ~w : (w | 0x80000000u);
}

// warp-0 suffix-scan over hist[nbins] (fallback only): find bin B with
// above(B) < need <= above(B)+hist[B]; outAbove = count in bins > B.
static __device__ __forceinline__ void find_bin(const unsigned int* hist,
                                                int nbins, unsigned int need,
                                                int* outB, unsigned int* outAbove,
                                                int tid) {
    if (tid < 32) {
        const int BPL = nbins / 32;
        unsigned int s = 0;
        for (int j = 0; j < BPL; j++) s += hist[tid * BPL + j];
        unsigned int v = s;
        #pragma unroll
        for (int d = 1; d < 32; d <<= 1) {
            unsigned int t = __shfl_down_sync(0xFFFFFFFFu, v, d);
            if (tid + d < 32) v += t;
        }
        unsigned int running = v - s;
        for (int j = BPL - 1; j >= 0; j--) {
            int b = tid * BPL + j;
            unsigned int n = hist[b];
            if (running < need && running + n >= need) {
                *outB = b;
                *outAbove = running;
            }
            running += n;
        }
    }
}

// block-parallel suffix scan over fb[FBINS]:
// fb[b] := (beg<<16)|beg, beg = count of keys in bins > b.
// *outTotal = grand total. *outBad |= 1 if a bin straddling rank K_OUT
// would scatter past SCAP. Requires full block, NT threads, warpsum[NT/32].
static __device__ __forceinline__ void scan_pack_block(unsigned int* fbx,
                                                       unsigned int* warpsum,
                                                       unsigned int* outTotal,
                                                       int* outBad, int tid) {
    const int lane = tid & 31;
    const int w    = tid >> 5;
    const int b0   = tid * BPT;

    unsigned int loc[BPT];
    unsigned int S = 0;
    #pragma unroll
    for (int j = 0; j < BPT; j++) { loc[j] = fbx[b0 + j]; S += loc[j]; }

    // warp inclusive suffix sum of per-thread sums
    unsigned int v = S;
    #pragma unroll
    for (int d = 1; d < 32; d <<= 1) {
        unsigned int t = __shfl_down_sync(0xFFFFFFFFu, v, d);
        if (lane + d < 32) v += t;
    }
    if (lane == 0) warpsum[w] = v;        // warp total
    __syncthreads();

    unsigned int wa = 0;                   // totals of warps above this one
    for (int w2 = w + 1; w2 < NT / 32; w2++) wa += warpsum[w2];
    if (tid == 0) *outTotal = wa + v;

    unsigned int running = wa + (v - S);  // exclusive suffix for this thread
    #pragma unroll
    for (int j = BPT - 1; j >= 0; j--) {
        unsigned int n = loc[j];
        if (running < K_OUT && running + n > SCAP) *outBad = 1;
        fbx[b0 + j] = (running << 16) | running;   // beg | cursor
        running += n;
    }
}

// ---------------------------------------------------------------------------
// Kernel A: streaming collect -> dense per-row candidate array.
// ---------------------------------------------------------------------------
__global__ __launch_bounds__(NTA)
void collect_kernel(const float* __restrict__ logits) {
    __shared__ unsigned long long stage[SUBCAP];     // 4 KB
    __shared__ unsigned int s_cnt, s_base;

    const int row = blockIdx.x / SUBS;
    const int sub = blockIdx.x % SUBS;
    const int tid = threadIdx.x;

    if (tid == 0) s_cnt = 0;
    __syncthreads();

    const int CHUNK4 = ROW_N / 4 / SUBS;             // 1024 uint4 per CTA
    const uint4* __restrict__ p =
        reinterpret_cast<const uint4*>(logits + (size_t)row * ROW_N) +
        sub * CHUNK4;
    const unsigned int base_idx = sub * (ROW_N / SUBS);

    #pragma unroll 4
    for (int i = tid; i < CHUNK4; i += NTA) {
        uint4 v = p[i];
        unsigned int ww[4] = {v.x, v.y, v.z, v.w};
        #pragma unroll
        for (int c = 0; c < 4; c++) {
            unsigned int u = ord32(ww[c]);
            if (u >= THETA) {                        // ~1.2% of elements
                unsigned int pos = atomicAdd(&s_cnt, 1u);
                if (pos < SUBCAP) {
                    unsigned int idx = base_idx + (unsigned int)(i * 4 + c);
                    stage[pos] = ((unsigned long long)u << 32) |
                                 (unsigned long long)(~idx);
                }
            }
        }
    }
    __syncthreads();

    if (tid == 0) {
        unsigned int cnt = s_cnt;
        // overflow poisons the row count -> n > CAP -> exact fallback
        unsigned int add = (cnt > SUBCAP) ? (SUBCAP + 0x40000u) : cnt;
        s_base = atomicAdd(&g_cnt[row], add);
        s_cnt = (cnt > SUBCAP) ? SUBCAP : cnt;
    }
    __syncthreads();

    const unsigned int cnt = s_cnt;
    const unsigned int base = s_base & 0x3FFFFu;
    unsigned long long* __restrict__ dst = g_cand + (size_t)row * CAP;
    for (unsigned int i = tid; i < cnt && base + i < CAP; i += NTA)
        dst[base + i] = stage[i];
}

// ---------------------------------------------------------------------------
// Kernel B: per-row counting-sort of candidates -> top-2048 indices.
// ---------------------------------------------------------------------------
__global__ __launch_bounds__(NT, 1)
void select_kernel(const float* __restrict__ logits, float* __restrict__ out) {
    __shared__ unsigned int       fb[FBINS];         // 16 KB
    __shared__ unsigned long long sorted[SCAP];      // 24 KB
    __shared__ unsigned int       warpsum[NT / 32];
    __shared__ int s_bad, s_T, s_R;
    __shared__ unsigned int s_m, s_hi, s_umax, s_dummy;

    const int row = blockIdx.x;
    const int tid = threadIdx.x;
    float* __restrict__ o = out + (size_t)row * K_OUT;
    const unsigned long long* __restrict__ cb = g_cand + (size_t)row * CAP;
    const unsigned int* __restrict__ rowbits =
        reinterpret_cast<const unsigned int*>(logits + (size_t)row * ROW_N);

    const unsigned int n = g_cnt[row];
    const bool good = (n >= K_OUT && n <= CAP);

    if (tid == 0) s_bad = good ? 0 : 1;
    #pragma unroll
    for (int b = tid; b < FBINS; b += NT) fb[b] = 0;
    __syncthreads();

    if (!s_bad) {
        // ============ good path: counting-sort ALL candidates ============
        for (unsigned int i = tid; i < n; i += NT) {
            unsigned int u = (unsigned int)(cb[i] >> 32);
            unsigned int fbin = (u - THETA) >> 12;
            if (fbin > FBINS - 1) fbin = FBINS - 1;
            atomicAdd(&fb[fbin], 1u);
        }
        __syncthreads();

        scan_pack_block(fb, warpsum, &s_m, &s_bad, tid);
        __syncthreads();

        if (!s_bad) {
            for (unsigned int i = tid; i < n; i += NT) {
                unsigned long long k64 = cb[i];
                unsigned int u = (unsigned int)(k64 >> 32);
                unsigned int fbin = (u - THETA) >> 12;
                if (fbin > FBINS - 1) fbin = FBINS - 1;
                unsigned int pos = atomicAdd(&fb[fbin], 1u) & 0xFFFFu;
                if (pos < SCAP) sorted[pos] = k64;
            }
            __syncthreads();

            // per-bin insertion sort (descending by full unique key)
            #pragma unroll
            for (int j = 0; j < BPT; j++) {
                int b = tid * BPT + j;
                unsigned int w = fb[b];
                int s = (int)(w >> 16);
                if (s >= K_OUT) continue;
                int e = (int)(w & 0xFFFFu);
                if (e > SCAP) e = SCAP;
                for (int x = s + 1; x < e; x++) {
                    unsigned long long v = sorted[x];
                    int y = x - 1;
                    while (y >= s && sorted[y] < v) {
                        sorted[y + 1] = sorted[y]; y--;
                    }
                    sorted[y + 1] = v;
                }
            }
            __syncthreads();

            #pragma unroll
            for (int j = tid; j < K_OUT; j += NT) {
                unsigned int idx = ~(unsigned int)(sorted[j] & 0xFFFFFFFFull);
                o[j] = (float)idx;
            }
            return;
        }
    }
    __syncthreads();

    // ============ exact full-row fallback (two-level + fine) ============
    for (int b = tid; b < FBINS; b += NT) fb[b] = 0;
    if (tid == 0) { s_T = -1; s_R = -1; s_hi = 0; s_umax = 0; }
    __syncthreads();

    for (int i = tid; i < ROW_N; i += NT) {
        unsigned int u = ord32(rowbits[i]);
        atomicAdd(&fb[u >> 21], 1u);
        atomicMax(&s_umax, u);
    }
    __syncthreads();
    find_bin(fb, PBINS, K_OUT, &s_T, &s_hi, tid);
    __syncthreads();
    const int Tb = s_T;
    const unsigned int hi = s_hi;
    const unsigned int umax = s_umax;
    __syncthreads();
    for (int b = tid; b < FBINS; b += NT) fb[b] = 0;
    __syncthreads();

    for (int i = tid; i < ROW_N; i += NT) {
        unsigned int u = ord32(rowbits[i]);
        if ((int)(u >> 21) == Tb)
            atomicAdd(&fb[(u >> 10) & (PBINS - 1)], 1u);
    }
    __syncthreads();
    find_bin(fb, PBINS, K_OUT - hi, &s_R, &s_dummy, tid);
    __syncthreads();
    const int Rb = s_R;
    const unsigned int uthr = ((unsigned int)Tb << 21) | ((unsigned int)Rb << 10);
    const unsigned long long range = (unsigned long long)(umax - uthr) + 1ull;
    __syncthreads();
    for (int b = tid; b < FBINS; b += NT) fb[b] = 0;
    if (tid == 0) s_bad = 0;
    __syncthreads();

    for (int i = tid; i < ROW_N; i += NT) {
        unsigned int u = ord32(rowbits[i]);
        if (u >= uthr) {
            unsigned int fbin = (unsigned int)
                (((unsigned long long)(u - uthr) * FBINS) / range);
            atomicAdd(&fb[fbin], 1u);
        }
    }
    __syncthreads();
    scan_pack_block(fb, warpsum, &s_m, &s_bad, tid);
    __syncthreads();
    const unsigned int m = s_m;
    if (m < K_OUT || m > SCAP || s_bad) {    // loud fail (degenerate dups)
        for (int j = tid; j < K_OUT; j += NT) o[j] = 1.2e5f;
        return;
    }

    for (int i = tid; i < ROW_N; i += NT) {
        unsigned int u = ord32(rowbits[i]);
        if (u >= uthr) {
            unsigned int fbin = (unsigned int)
                (((unsigned long long)(u - uthr) * FBINS) / range);
            unsigned int pos = atomicAdd(&fb[fbin], 1u) & 0xFFFFu;
            if (pos < SCAP) {
                sorted[pos] = ((unsigned long long)u << 32) |
                              (unsigned long long)(~(unsigned int)i);
            }
        }
    }
    __syncthreads();

    #pragma unroll
    for (int j = 0; j < BPT; j++) {
        int b = tid * BPT + j;
        unsigned int w = fb[b];
        int s = (int)(w >> 16);
        if (s >= K_OUT) continue;
        int e = (int)(w & 0xFFFFu);
        if (e > SCAP) e = SCAP;
        for (int x = s + 1; x < e; x++) {
            unsigned long long v = sorted[x];
            int y = x - 1;
            while (y >= s && sorted[y] < v) { sorted[y + 1] = sorted[y]; y--; }
            sorted[y + 1] = v;
        }
    }
    __syncthreads();

    for (int j = tid; j < K_OUT; j += NT) {
        unsigned int idx = ~(unsigned int)(sorted[j] & 0xFFFFFFFFull);
        o[j] = (float)idx;
    }
}

// ---------------------------------------------------------------------------
extern "C" void kernel_launch(void* const* d_in, const int* in_sizes, int n_in,
                              void* d_out, int out_size) {
    const float* logits = (const float*)d_in[0];
    long long best = -1;
    for (int i = 0; i < n_in; i++) {
        if ((long long)in_sizes[i] > best) {
            best = in_sizes[i];
            logits = (const float*)d_in[i];
        }
    }
    void* cnt_ptr = nullptr;
    cudaGetSymbolAddress(&cnt_ptr, g_cnt);
    cudaMemsetAsync(cnt_ptr, 0, ROWS * sizeof(unsigned int), 0);
    collect_kernel<<<ROWS * SUBS, NTA>>>(logits);
    select_kernel<<<ROWS, NT>>>(logits, (float*)d_out);
}